// round 1
// baseline (speedup 1.0000x reference)
#include <cuda_runtime.h>
#include <math_constants.h>

#define NN 25000
#define EE 250000
#define HH 4
#define DD 64
#define HD 256   // H*D

// ---------------- scratch (device globals; no allocation allowed) -------------
__device__ float g_feat[NN * HD];  // x @ W for current layer
__device__ float g_h[NN * HD];     // layer output (next layer input)
__device__ float g_el[NN * HH];
__device__ float g_er[NN * HH];
__device__ float g_mf[NN * HH];    // segment max
__device__ float g_s[NN * HH];     // segment sum
__device__ float g_e[EE * HH];     // edge scores -> exp numerators

// ---------------- helpers ----------------------------------------------------
__device__ __forceinline__ void atomicMaxFloat(float* addr, float val) {
    int old = __float_as_int(*addr);
    while (__int_as_float(old) < val) {
        int assumed = old;
        old = atomicCAS((int*)addr, assumed, __float_as_int(val));
        if (old == assumed) break;
    }
}

__device__ __forceinline__ void red_add_v4(float* p, float4 v) {
    asm volatile("red.global.add.v4.f32 [%0], {%1, %2, %3, %4};"
                 :: "l"(p), "f"(v.x), "f"(v.y), "f"(v.z), "f"(v.w) : "memory");
}

// ---------------- SGEMM 128x128, BK=8, 8x8 per thread, fp32 ------------------
// A: [NN,256] row-major, B: [256,256] row-major, C = A@B
__global__ __launch_bounds__(256) void sgemm_kernel(const float* __restrict__ A,
                                                    const float* __restrict__ B,
                                                    float* __restrict__ C) {
    __shared__ float As[8][128];
    __shared__ float Bs[8][128];
    const int tid = threadIdx.x;
    const int bm = blockIdx.x * 128;
    const int bn = blockIdx.y * 128;
    const int tx = tid & 15, ty = tid >> 4;

    float acc[8][8];
#pragma unroll
    for (int i = 0; i < 8; i++)
#pragma unroll
        for (int j = 0; j < 8; j++) acc[i][j] = 0.f;

    const int lr = tid >> 1, lc = (tid & 1) * 4;   // A tile load coords
    const int br = tid >> 5, bc = (tid & 31) * 4;  // B tile load coords

    for (int kk = 0; kk < 256; kk += 8) {
        float4 av = make_float4(0.f, 0.f, 0.f, 0.f);
        int arow = bm + lr;
        if (arow < NN) av = *(const float4*)(A + arow * 256 + kk + lc);
        As[lc + 0][lr] = av.x;
        As[lc + 1][lr] = av.y;
        As[lc + 2][lr] = av.z;
        As[lc + 3][lr] = av.w;
        *(float4*)&Bs[br][bc] = *(const float4*)(B + (kk + br) * 256 + bn + bc);
        __syncthreads();
#pragma unroll
        for (int k = 0; k < 8; k++) {
            float a[8], b[8];
            *(float4*)&a[0] = *(const float4*)&As[k][ty * 8];
            *(float4*)&a[4] = *(const float4*)&As[k][ty * 8 + 4];
            *(float4*)&b[0] = *(const float4*)&Bs[k][tx * 8];
            *(float4*)&b[4] = *(const float4*)&Bs[k][tx * 8 + 4];
#pragma unroll
            for (int i = 0; i < 8; i++)
#pragma unroll
                for (int j = 0; j < 8; j++) acc[i][j] += a[i] * b[j];
        }
        __syncthreads();
    }
#pragma unroll
    for (int i = 0; i < 8; i++) {
        int row = bm + ty * 8 + i;
        if (row < NN) {
            *(float4*)(C + row * 256 + bn + tx * 8) =
                make_float4(acc[i][0], acc[i][1], acc[i][2], acc[i][3]);
            *(float4*)(C + row * 256 + bn + tx * 8 + 4) =
                make_float4(acc[i][4], acc[i][5], acc[i][6], acc[i][7]);
        }
    }
}

// ---------------- per-node prep: el/er, init max/sum, zero output -------------
// one warp per node; lane covers 8 contiguous floats (all within one head)
__global__ __launch_bounds__(256) void node_prep_kernel(const float* __restrict__ al,
                                                        const float* __restrict__ ar) {
    int warp = (blockIdx.x * blockDim.x + threadIdx.x) >> 5;
    int lane = threadIdx.x & 31;
    if (warp >= NN) return;

    const float4* f = (const float4*)(g_feat + warp * HD);
    float4 f0 = f[lane * 2], f1 = f[lane * 2 + 1];
    float4 a0 = ((const float4*)al)[lane * 2], a1 = ((const float4*)al)[lane * 2 + 1];
    float4 r0 = ((const float4*)ar)[lane * 2], r1 = ((const float4*)ar)[lane * 2 + 1];

    float pel = f0.x * a0.x + f0.y * a0.y + f0.z * a0.z + f0.w * a0.w +
                f1.x * a1.x + f1.y * a1.y + f1.z * a1.z + f1.w * a1.w;
    float per = f0.x * r0.x + f0.y * r0.y + f0.z * r0.z + f0.w * r0.w +
                f1.x * r1.x + f1.y * r1.y + f1.z * r1.z + f1.w * r1.w;
#pragma unroll
    for (int off = 4; off >= 1; off >>= 1) {
        pel += __shfl_down_sync(0xffffffffu, pel, off, 8);
        per += __shfl_down_sync(0xffffffffu, per, off, 8);
    }
    if ((lane & 7) == 0) {
        int h = lane >> 3;
        g_el[warp * HH + h] = pel;
        g_er[warp * HH + h] = per;
        g_mf[warp * HH + h] = -CUDART_INF_F;
        g_s[warp * HH + h] = 0.f;
    }
    // zero the aggregation target
    float4 z = make_float4(0.f, 0.f, 0.f, 0.f);
    ((float4*)(g_h + warp * HD))[lane * 2] = z;
    ((float4*)(g_h + warp * HD))[lane * 2 + 1] = z;
}

// ---------------- edge pass 1: leaky_relu score + segment max -----------------
__global__ __launch_bounds__(256) void edge_max_kernel(const int* __restrict__ src,
                                                       const int* __restrict__ dst) {
    int i = blockIdx.x * blockDim.x + threadIdx.x;
    if (i >= EE * HH) return;
    int e = i >> 2, h = i & 3;
    int sN = src[e], dN = dst[e];
    float v = g_el[sN * HH + h] + g_er[dN * HH + h];
    v = v > 0.f ? v : 0.2f * v;
    g_e[i] = v;
    atomicMaxFloat(&g_mf[dN * HH + h], v);
}

// ---------------- edge pass 2: exp + segment sum ------------------------------
__global__ __launch_bounds__(256) void edge_sum_kernel(const int* __restrict__ dst) {
    int i = blockIdx.x * blockDim.x + threadIdx.x;
    if (i >= EE * HH) return;
    int e = i >> 2, h = i & 3;
    int dN = dst[e];
    float a = expf(g_e[i] - g_mf[dN * HH + h]);
    g_e[i] = a;
    atomicAdd(&g_s[dN * HH + h], a);
}

// ---------------- edge pass 3: weighted scatter aggregation -------------------
// one warp per edge; lane handles 8 floats (one head's sub-slice)
__global__ __launch_bounds__(256) void edge_aggr_kernel(const int* __restrict__ src,
                                                        const int* __restrict__ dst) {
    int e = (blockIdx.x * blockDim.x + threadIdx.x) >> 5;
    int lane = threadIdx.x & 31;
    if (e >= EE) return;
    int sN = __shfl_sync(0xffffffffu, lane == 0 ? src[e] : 0, 0);
    int dN = __shfl_sync(0xffffffffu, lane == 0 ? dst[e] : 0, 0);
    int h = lane >> 3;
    float alpha = g_e[e * HH + h] / g_s[dN * HH + h];

    const float4* f = (const float4*)(g_feat + sN * HD);
    float4 v0 = f[lane * 2], v1 = f[lane * 2 + 1];
    v0.x *= alpha; v0.y *= alpha; v0.z *= alpha; v0.w *= alpha;
    v1.x *= alpha; v1.y *= alpha; v1.z *= alpha; v1.w *= alpha;
    float* p = g_h + dN * HD + lane * 8;
    red_add_v4(p, v0);
    red_add_v4(p + 4, v1);
}

// ---------------- bias + relu -------------------------------------------------
__global__ __launch_bounds__(256) void bias_relu_kernel(const float* __restrict__ b) {
    int i = blockIdx.x * blockDim.x + threadIdx.x;  // in float4 units
    if (i >= NN * HD / 4) return;
    float4 v = ((float4*)g_h)[i];
    const float4 bv = ((const float4*)b)[i & 63];
    v.x = fmaxf(v.x + bv.x, 0.f);
    v.y = fmaxf(v.y + bv.y, 0.f);
    v.z = fmaxf(v.z + bv.z, 0.f);
    v.w = fmaxf(v.w + bv.w, 0.f);
    ((float4*)g_h)[i] = v;
}

// ---------------- final dot scores (pos then neg) ------------------------------
__global__ __launch_bounds__(256) void score_kernel(const int* __restrict__ src,
                                                    const int* __restrict__ dst,
                                                    const int* __restrict__ nsrc,
                                                    const int* __restrict__ ndst,
                                                    float* __restrict__ out) {
    int w = (blockIdx.x * blockDim.x + threadIdx.x) >> 5;
    int lane = threadIdx.x & 31;
    if (w >= 2 * EE) return;
    bool pos = w < EE;
    int e = pos ? w : w - EE;
    int uN = pos ? src[e] : nsrc[e];
    int vN = pos ? dst[e] : ndst[e];

    const float4* fu = (const float4*)(g_h + uN * HD);
    const float4* fv = (const float4*)(g_h + vN * HD);
    float4 u0 = fu[lane * 2], u1 = fu[lane * 2 + 1];
    float4 v0 = fv[lane * 2], v1 = fv[lane * 2 + 1];
    float d = u0.x * v0.x + u0.y * v0.y + u0.z * v0.z + u0.w * v0.w +
              u1.x * v1.x + u1.y * v1.y + u1.z * v1.z + u1.w * v1.w;
#pragma unroll
    for (int off = 4; off >= 1; off >>= 1) d += __shfl_down_sync(0xffffffffu, d, off, 8);
    if ((lane & 7) == 0) {
        int h = lane >> 3;
        out[(pos ? 0 : EE * HH) + e * HH + h] = d;
    }
}

// ---------------- launch -------------------------------------------------------
extern "C" void kernel_launch(void* const* d_in, const int* in_sizes, int n_in,
                              void* d_out, int out_size) {
    const float* x    = (const float*)d_in[0];
    const int* src    = (const int*)d_in[1];
    const int* dst    = (const int*)d_in[2];
    const int* nsrc   = (const int*)d_in[3];
    const int* ndst   = (const int*)d_in[4];
    const float* W[3]  = {(const float*)d_in[5], (const float*)d_in[9],  (const float*)d_in[13]};
    const float* al[3] = {(const float*)d_in[6], (const float*)d_in[10], (const float*)d_in[14]};
    const float* ar[3] = {(const float*)d_in[7], (const float*)d_in[11], (const float*)d_in[15]};
    const float* bb[3] = {(const float*)d_in[8], (const float*)d_in[12], (const float*)d_in[16]};
    float* out = (float*)d_out;

    float* hbuf = nullptr;
    cudaGetSymbolAddress((void**)&hbuf, g_h);
    float* featbuf = nullptr;
    cudaGetSymbolAddress((void**)&featbuf, g_feat);

    dim3 gemm_grid((NN + 127) / 128, 2);
    const int nprep_blocks = (NN * 32 + 255) / 256;
    const int eh_blocks    = (EE * HH + 255) / 256;
    const int aggr_blocks  = (EE * 32 + 255) / 256;
    const int bias_blocks  = (NN * HD / 4 + 255) / 256;
    const int score_blocks = (2 * EE * 32 + 255) / 256;

    const float* layer_in = x;
    for (int l = 0; l < 3; l++) {
        sgemm_kernel<<<gemm_grid, 256>>>(layer_in, W[l], featbuf);
        node_prep_kernel<<<nprep_blocks, 256>>>(al[l], ar[l]);
        edge_max_kernel<<<eh_blocks, 256>>>(src, dst);
        edge_sum_kernel<<<eh_blocks, 256>>>(dst);
        edge_aggr_kernel<<<aggr_blocks, 256>>>(src, dst);
        bias_relu_kernel<<<bias_blocks, 256>>>(bb[l]);
        layer_in = hbuf;
    }
    score_kernel<<<score_blocks, 256>>>(src, dst, nsrc, ndst, out);
}

// round 2
// speedup vs baseline: 1.2943x; 1.2943x over previous
#include <cuda_runtime.h>
#include <cuda_bf16.h>
#include <math_constants.h>
#include <stdint.h>

#define NN 25000
#define EE 250000
#define HH 4
#define DD 64
#define HD 256   // H*D

// ---------------- scratch (device globals; no allocation allowed) -------------
__device__ float g_feat[NN * HD];  // x @ W for current layer
__device__ float g_h[NN * HD];     // layer output (next layer input)
__device__ float g_el[NN * HH];
__device__ float g_er[NN * HH];
__device__ float g_mf[NN * HH];    // segment max
__device__ float g_s[NN * HH];     // segment sum
__device__ float g_e[EE * HH];     // edge scores -> exp numerators

// ---------------- helpers ----------------------------------------------------
__device__ __forceinline__ void atomicMaxFloat(float* addr, float val) {
    int old = __float_as_int(*addr);
    while (__int_as_float(old) < val) {
        int assumed = old;
        old = atomicCAS((int*)addr, assumed, __float_as_int(val));
        if (old == assumed) break;
    }
}

__device__ __forceinline__ void red_add_v4(float* p, float4 v) {
    asm volatile("red.global.add.v4.f32 [%0], {%1, %2, %3, %4};"
                 :: "l"(p), "f"(v.x), "f"(v.y), "f"(v.z), "f"(v.w) : "memory");
}

__device__ __forceinline__ void mma16816(float* d, const uint32_t* a, const uint32_t* b) {
    asm volatile(
        "mma.sync.aligned.m16n8k16.row.col.f32.bf16.bf16.f32 "
        "{%0,%1,%2,%3}, {%4,%5,%6,%7}, {%8,%9}, {%0,%1,%2,%3};"
        : "+f"(d[0]), "+f"(d[1]), "+f"(d[2]), "+f"(d[3])
        : "r"(a[0]), "r"(a[1]), "r"(a[2]), "r"(a[3]), "r"(b[0]), "r"(b[1]));
}

__device__ __forceinline__ void split_bf16(float f, __nv_bfloat16& h, __nv_bfloat16& l) {
    h = __float2bfloat16(f);
    l = __float2bfloat16(f - __bfloat162float(h));
}

// ---------------- GEMM via bf16-split tensor cores ---------------------------
// C[M,256] = A[M,256] @ B[256,256], fp32 in/out, ~fp32 precision via
// A = Ah + Al, B = Bh + Bl (bf16), C = Ah*Bh + Ah*Bl + Al*Bh (fp32 accum).
// Block tile 128x128, BK=32, 8 warps (2m x 4n), warp tile 64x32 (4x4 atoms).
#define ASTRIDE 40   // bf16 units per A shared row (32 + 8 pad, 80B: frag loads conflict-free, 16B aligned)
#define BSTRIDE 17   // uint32 (k-pair) units per B shared row (16 + 1 pad: store conflict-free)

__global__ __launch_bounds__(256) void gemm_bf16x3(const float* __restrict__ A,
                                                   const float* __restrict__ B,
                                                   float* __restrict__ C) {
    __shared__ __align__(16) __nv_bfloat16 Ah[128 * ASTRIDE];
    __shared__ __align__(16) __nv_bfloat16 Al[128 * ASTRIDE];
    __shared__ uint32_t BpH[128 * BSTRIDE];  // packed (k, k+1) bf16 pairs, layout [n][k2]
    __shared__ uint32_t BpL[128 * BSTRIDE];

    const int tid = threadIdx.x;
    const int bm = blockIdx.x * 128;
    const int bn = blockIdx.y * 128;
    const int lane = tid & 31;
    const int wid = tid >> 5;
    const int wm = (wid >> 2) * 64;   // warp row offset within block: 0 / 64
    const int wn = (wid & 3) * 32;    // warp col offset within block
    const int g  = lane >> 2;         // group id 0..7
    const int c  = lane & 3;          // thread-in-group
    const int c2 = c * 2;

    float acc[4][4][4];
#pragma unroll
    for (int i = 0; i < 4; i++)
#pragma unroll
        for (int j = 0; j < 4; j++)
#pragma unroll
            for (int t = 0; t < 4; t++) acc[i][j][t] = 0.f;

    // A loader: thread -> row tid>>1 (0..127), col half (tid&1)*16
    const int arow = tid >> 1;
    const int alc  = (tid & 1) * 16;
    const int agr  = bm + arow;
    // B loader: thread -> n = tid&127, k half (tid>>7)*16
    const int bln  = tid & 127;
    const int blk  = (tid >> 7) * 16;

    float pa[16];
    float pb[16];

    // prefetch stage 0
    {
        if (agr < NN) {
            const float4* s = (const float4*)(A + agr * 256 + 0 + alc);
#pragma unroll
            for (int q = 0; q < 4; q++) { float4 v = s[q]; pa[q*4+0]=v.x; pa[q*4+1]=v.y; pa[q*4+2]=v.z; pa[q*4+3]=v.w; }
        } else {
#pragma unroll
            for (int q = 0; q < 16; q++) pa[q] = 0.f;
        }
#pragma unroll
        for (int j = 0; j < 16; j++) pb[j] = B[(0 + blk + j) * 256 + bn + bln];
    }

    for (int kk = 0; kk < 256; kk += 32) {
        // ---- store prefetched panel to shared (split hi/lo) ----
        {
            uint32_t packedH[8], packedL[8];
#pragma unroll
            for (int t = 0; t < 8; t++) {
                __nv_bfloat16 h0, l0, h1, l1;
                split_bf16(pa[2*t],   h0, l0);
                split_bf16(pa[2*t+1], h1, l1);
                __nv_bfloat162 ph = {h0, h1}, pl = {l0, l1};
                packedH[t] = *(uint32_t*)&ph;
                packedL[t] = *(uint32_t*)&pl;
            }
            uint32_t* dstH = (uint32_t*)&Ah[arow * ASTRIDE + alc];
            uint32_t* dstL = (uint32_t*)&Al[arow * ASTRIDE + alc];
            *(uint4*)(dstH)     = make_uint4(packedH[0], packedH[1], packedH[2], packedH[3]);
            *(uint4*)(dstH + 4) = make_uint4(packedH[4], packedH[5], packedH[6], packedH[7]);
            *(uint4*)(dstL)     = make_uint4(packedL[0], packedL[1], packedL[2], packedL[3]);
            *(uint4*)(dstL + 4) = make_uint4(packedL[4], packedL[5], packedL[6], packedL[7]);
        }
        {
            const int base = bln * BSTRIDE + (blk >> 1);
#pragma unroll
            for (int t = 0; t < 8; t++) {
                __nv_bfloat16 h0, l0, h1, l1;
                split_bf16(pb[2*t],   h0, l0);
                split_bf16(pb[2*t+1], h1, l1);
                __nv_bfloat162 ph = {h0, h1}, pl = {l0, l1};
                BpH[base + t] = *(uint32_t*)&ph;
                BpL[base + t] = *(uint32_t*)&pl;
            }
        }
        __syncthreads();

        // ---- prefetch next stage ----
        if (kk + 32 < 256) {
            if (agr < NN) {
                const float4* s = (const float4*)(A + agr * 256 + kk + 32 + alc);
#pragma unroll
                for (int q = 0; q < 4; q++) { float4 v = s[q]; pa[q*4+0]=v.x; pa[q*4+1]=v.y; pa[q*4+2]=v.z; pa[q*4+3]=v.w; }
            }
#pragma unroll
            for (int j = 0; j < 16; j++) pb[j] = B[(kk + 32 + blk + j) * 256 + bn + bln];
        }

        // ---- compute: 2 x k16 steps ----
#pragma unroll
        for (int ks = 0; ks < 2; ks++) {
            const int ko = ks * 16;  // bf16 k offset in A shared
            const int k2 = ks * 8;   // k-pair offset in B shared
            uint32_t bh[4][2], bl[4][2];
#pragma unroll
            for (int j = 0; j < 4; j++) {
                int n = wn + j * 8 + g;
                bh[j][0] = BpH[n * BSTRIDE + k2 + c];
                bh[j][1] = BpH[n * BSTRIDE + k2 + c + 4];
                bl[j][0] = BpL[n * BSTRIDE + k2 + c];
                bl[j][1] = BpL[n * BSTRIDE + k2 + c + 4];
            }
#pragma unroll
            for (int i = 0; i < 4; i++) {
                const int r0 = wm + i * 16 + g;
                uint32_t ah[4], al_[4];
                ah[0]  = *(const uint32_t*)&Ah[r0 * ASTRIDE + ko + c2];
                ah[1]  = *(const uint32_t*)&Ah[(r0 + 8) * ASTRIDE + ko + c2];
                ah[2]  = *(const uint32_t*)&Ah[r0 * ASTRIDE + ko + c2 + 8];
                ah[3]  = *(const uint32_t*)&Ah[(r0 + 8) * ASTRIDE + ko + c2 + 8];
                al_[0] = *(const uint32_t*)&Al[r0 * ASTRIDE + ko + c2];
                al_[1] = *(const uint32_t*)&Al[(r0 + 8) * ASTRIDE + ko + c2];
                al_[2] = *(const uint32_t*)&Al[r0 * ASTRIDE + ko + c2 + 8];
                al_[3] = *(const uint32_t*)&Al[(r0 + 8) * ASTRIDE + ko + c2 + 8];
#pragma unroll
                for (int j = 0; j < 4; j++) {
                    mma16816(acc[i][j], ah, bh[j]);   // Ah * Bh
                    mma16816(acc[i][j], ah, bl[j]);   // Ah * Bl
                    mma16816(acc[i][j], al_, bh[j]);  // Al * Bh
                }
            }
        }
        __syncthreads();
    }

    // ---- epilogue ----
#pragma unroll
    for (int i = 0; i < 4; i++) {
        const int r = bm + wm + i * 16 + g;
#pragma unroll
        for (int j = 0; j < 4; j++) {
            const int col = bn + wn + j * 8 + c2;
            if (r < NN)
                *(float2*)(C + r * 256 + col) = make_float2(acc[i][j][0], acc[i][j][1]);
            if (r + 8 < NN)
                *(float2*)(C + (r + 8) * 256 + col) = make_float2(acc[i][j][2], acc[i][j][3]);
        }
    }
}

// ---------------- per-node prep: el/er, init max/sum, zero output -------------
__global__ __launch_bounds__(256) void node_prep_kernel(const float* __restrict__ al,
                                                        const float* __restrict__ ar) {
    int warp = (blockIdx.x * blockDim.x + threadIdx.x) >> 5;
    int lane = threadIdx.x & 31;
    if (warp >= NN) return;

    const float4* f = (const float4*)(g_feat + warp * HD);
    float4 f0 = f[lane * 2], f1 = f[lane * 2 + 1];
    float4 a0 = ((const float4*)al)[lane * 2], a1 = ((const float4*)al)[lane * 2 + 1];
    float4 r0 = ((const float4*)ar)[lane * 2], r1 = ((const float4*)ar)[lane * 2 + 1];

    float pel = f0.x * a0.x + f0.y * a0.y + f0.z * a0.z + f0.w * a0.w +
                f1.x * a1.x + f1.y * a1.y + f1.z * a1.z + f1.w * a1.w;
    float per = f0.x * r0.x + f0.y * r0.y + f0.z * r0.z + f0.w * r0.w +
                f1.x * r1.x + f1.y * r1.y + f1.z * r1.z + f1.w * r1.w;
#pragma unroll
    for (int off = 4; off >= 1; off >>= 1) {
        pel += __shfl_down_sync(0xffffffffu, pel, off, 8);
        per += __shfl_down_sync(0xffffffffu, per, off, 8);
    }
    if ((lane & 7) == 0) {
        int h = lane >> 3;
        g_el[warp * HH + h] = pel;
        g_er[warp * HH + h] = per;
        g_mf[warp * HH + h] = -CUDART_INF_F;
        g_s[warp * HH + h] = 0.f;
    }
    float4 z = make_float4(0.f, 0.f, 0.f, 0.f);
    ((float4*)(g_h + warp * HD))[lane * 2] = z;
    ((float4*)(g_h + warp * HD))[lane * 2 + 1] = z;
}

// ---------------- edge pass 1: leaky_relu score + segment max -----------------
__global__ __launch_bounds__(256) void edge_max_kernel(const int* __restrict__ src,
                                                       const int* __restrict__ dst) {
    int i = blockIdx.x * blockDim.x + threadIdx.x;
    if (i >= EE * HH) return;
    int e = i >> 2, h = i & 3;
    int sN = src[e], dN = dst[e];
    float v = g_el[sN * HH + h] + g_er[dN * HH + h];
    v = v > 0.f ? v : 0.2f * v;
    g_e[i] = v;
    atomicMaxFloat(&g_mf[dN * HH + h], v);
}

// ---------------- edge pass 2: exp + segment sum ------------------------------
__global__ __launch_bounds__(256) void edge_sum_kernel(const int* __restrict__ dst) {
    int i = blockIdx.x * blockDim.x + threadIdx.x;
    if (i >= EE * HH) return;
    int e = i >> 2, h = i & 3;
    int dN = dst[e];
    float a = expf(g_e[i] - g_mf[dN * HH + h]);
    g_e[i] = a;
    atomicAdd(&g_s[dN * HH + h], a);
}

// ---------------- edge pass 3: weighted scatter aggregation -------------------
__global__ __launch_bounds__(256) void edge_aggr_kernel(const int* __restrict__ src,
                                                        const int* __restrict__ dst) {
    int e = (blockIdx.x * blockDim.x + threadIdx.x) >> 5;
    int lane = threadIdx.x & 31;
    if (e >= EE) return;
    int sN = __shfl_sync(0xffffffffu, lane == 0 ? src[e] : 0, 0);
    int dN = __shfl_sync(0xffffffffu, lane == 0 ? dst[e] : 0, 0);
    int h = lane >> 3;
    float alpha = g_e[e * HH + h] / g_s[dN * HH + h];

    const float4* f = (const float4*)(g_feat + sN * HD);
    float4 v0 = f[lane * 2], v1 = f[lane * 2 + 1];
    v0.x *= alpha; v0.y *= alpha; v0.z *= alpha; v0.w *= alpha;
    v1.x *= alpha; v1.y *= alpha; v1.z *= alpha; v1.w *= alpha;
    float* p = g_h + dN * HD + lane * 8;
    red_add_v4(p, v0);
    red_add_v4(p + 4, v1);
}

// ---------------- bias + relu -------------------------------------------------
__global__ __launch_bounds__(256) void bias_relu_kernel(const float* __restrict__ b) {
    int i = blockIdx.x * blockDim.x + threadIdx.x;  // in float4 units
    if (i >= NN * HD / 4) return;
    float4 v = ((float4*)g_h)[i];
    const float4 bv = ((const float4*)b)[i & 63];
    v.x = fmaxf(v.x + bv.x, 0.f);
    v.y = fmaxf(v.y + bv.y, 0.f);
    v.z = fmaxf(v.z + bv.z, 0.f);
    v.w = fmaxf(v.w + bv.w, 0.f);
    ((float4*)g_h)[i] = v;
}

// ---------------- final dot scores (pos then neg) ------------------------------
__global__ __launch_bounds__(256) void score_kernel(const int* __restrict__ src,
                                                    const int* __restrict__ dst,
                                                    const int* __restrict__ nsrc,
                                                    const int* __restrict__ ndst,
                                                    float* __restrict__ out) {
    int w = (blockIdx.x * blockDim.x + threadIdx.x) >> 5;
    int lane = threadIdx.x & 31;
    if (w >= 2 * EE) return;
    bool pos = w < EE;
    int e = pos ? w : w - EE;
    int uN = pos ? src[e] : nsrc[e];
    int vN = pos ? dst[e] : ndst[e];

    const float4* fu = (const float4*)(g_h + uN * HD);
    const float4* fv = (const float4*)(g_h + vN * HD);
    float4 u0 = fu[lane * 2], u1 = fu[lane * 2 + 1];
    float4 v0 = fv[lane * 2], v1 = fv[lane * 2 + 1];
    float d = u0.x * v0.x + u0.y * v0.y + u0.z * v0.z + u0.w * v0.w +
              u1.x * v1.x + u1.y * v1.y + u1.z * v1.z + u1.w * v1.w;
#pragma unroll
    for (int off = 4; off >= 1; off >>= 1) d += __shfl_down_sync(0xffffffffu, d, off, 8);
    if ((lane & 7) == 0) {
        int h = lane >> 3;
        out[(pos ? 0 : EE * HH) + e * HH + h] = d;
    }
}

// ---------------- launch -------------------------------------------------------
extern "C" void kernel_launch(void* const* d_in, const int* in_sizes, int n_in,
                              void* d_out, int out_size) {
    const float* x    = (const float*)d_in[0];
    const int* src    = (const int*)d_in[1];
    const int* dst    = (const int*)d_in[2];
    const int* nsrc   = (const int*)d_in[3];
    const int* ndst   = (const int*)d_in[4];
    const float* W[3]  = {(const float*)d_in[5], (const float*)d_in[9],  (const float*)d_in[13]};
    const float* al[3] = {(const float*)d_in[6], (const float*)d_in[10], (const float*)d_in[14]};
    const float* ar[3] = {(const float*)d_in[7], (const float*)d_in[11], (const float*)d_in[15]};
    const float* bb[3] = {(const float*)d_in[8], (const float*)d_in[12], (const float*)d_in[16]};
    float* out = (float*)d_out;

    float* hbuf = nullptr;
    cudaGetSymbolAddress((void**)&hbuf, g_h);
    float* featbuf = nullptr;
    cudaGetSymbolAddress((void**)&featbuf, g_feat);

    dim3 gemm_grid((NN + 127) / 128, 2);
    const int nprep_blocks = (NN * 32 + 255) / 256;
    const int eh_blocks    = (EE * HH + 255) / 256;
    const int aggr_blocks  = (EE * 32 + 255) / 256;
    const int bias_blocks  = (NN * HD / 4 + 255) / 256;
    const int score_blocks = (2 * EE * 32 + 255) / 256;

    const float* layer_in = x;
    for (int l = 0; l < 3; l++) {
        gemm_bf16x3<<<gemm_grid, 256>>>(layer_in, W[l], featbuf);
        node_prep_kernel<<<nprep_blocks, 256>>>(al[l], ar[l]);
        edge_max_kernel<<<eh_blocks, 256>>>(src, dst);
        edge_sum_kernel<<<eh_blocks, 256>>>(dst);
        edge_aggr_kernel<<<aggr_blocks, 256>>>(src, dst);
        bias_relu_kernel<<<bias_blocks, 256>>>(bb[l]);
        layer_in = hbuf;
    }
    score_kernel<<<score_blocks, 256>>>(src, dst, nsrc, ndst, out);
}

// round 3
// speedup vs baseline: 1.9920x; 1.5390x over previous
#include <cuda_runtime.h>
#include <cuda_bf16.h>
#include <cuda_fp16.h>
#include <math_constants.h>
#include <stdint.h>

#define NN 25000
#define EE 250000
#define HH 4
#define DD 64
#define HD 256   // H*D

// ---------------- scratch (device globals; no allocation allowed) -------------
__device__ float g_feat[NN * HD];   // x @ W for current layer
__device__ float g_h[NN * HD];      // layer output (next layer input), fp32
__device__ __half g_hh[NN * HD];    // final layer output, fp16 (score input)
__device__ float g_el[NN * HH];
__device__ float g_er[NN * HH];
// CSR by dst (built once per launch; dst is identical for all 3 layers)
__device__ int g_cnt[NN];
__device__ int g_off[NN + 1];
__device__ int g_cur[NN];
__device__ int g_csr_src[EE];

// ---------------- helpers ----------------------------------------------------
__device__ __forceinline__ void mma16816(float* d, const uint32_t* a, const uint32_t* b) {
    asm volatile(
        "mma.sync.aligned.m16n8k16.row.col.f32.bf16.bf16.f32 "
        "{%0,%1,%2,%3}, {%4,%5,%6,%7}, {%8,%9}, {%0,%1,%2,%3};"
        : "+f"(d[0]), "+f"(d[1]), "+f"(d[2]), "+f"(d[3])
        : "r"(a[0]), "r"(a[1]), "r"(a[2]), "r"(a[3]), "r"(b[0]), "r"(b[1]));
}

__device__ __forceinline__ void split_bf16(float f, __nv_bfloat16& h, __nv_bfloat16& l) {
    h = __float2bfloat16(f);
    l = __float2bfloat16(f - __bfloat162float(h));
}

// ---------------- CSR build ---------------------------------------------------
__global__ __launch_bounds__(256) void csr_zero_kernel() {
    int i = blockIdx.x * blockDim.x + threadIdx.x;
    if (i < NN) g_cnt[i] = 0;
}

__global__ __launch_bounds__(256) void csr_hist_kernel(const int* __restrict__ dst) {
    int i = blockIdx.x * blockDim.x + threadIdx.x;
    if (i < EE) atomicAdd(&g_cnt[dst[i]], 1);
}

// single block, 1024 threads; each thread owns 25 consecutive nodes
__global__ __launch_bounds__(1024) void csr_scan_kernel() {
    __shared__ int part[1024];
    const int tid = threadIdx.x;
    const int base = tid * 25;
    int loc[25];
    int s = 0;
#pragma unroll
    for (int j = 0; j < 25; j++) {
        int idx = base + j;
        int c = (idx < NN) ? g_cnt[idx] : 0;
        loc[j] = s;
        s += c;
    }
    part[tid] = s;
    __syncthreads();
    for (int off = 1; off < 1024; off <<= 1) {
        int v = (tid >= off) ? part[tid - off] : 0;
        __syncthreads();
        part[tid] += v;
        __syncthreads();
    }
    const int excl = (tid == 0) ? 0 : part[tid - 1];
#pragma unroll
    for (int j = 0; j < 25; j++) {
        int idx = base + j;
        if (idx < NN) {
            int o = excl + loc[j];
            g_off[idx] = o;
            g_cur[idx] = o;
        }
    }
    if (tid == 0) g_off[NN] = EE;
}

__global__ __launch_bounds__(256) void csr_scatter_kernel(const int* __restrict__ src,
                                                          const int* __restrict__ dst) {
    int e = blockIdx.x * blockDim.x + threadIdx.x;
    if (e >= EE) return;
    int slot = atomicAdd(&g_cur[dst[e]], 1);
    g_csr_src[slot] = src[e];
}

// ---------------- GEMM via bf16-split tensor cores ---------------------------
#define ASTRIDE 40
#define BSTRIDE 17

__global__ __launch_bounds__(256) void gemm_bf16x3(const float* __restrict__ A,
                                                   const float* __restrict__ B,
                                                   float* __restrict__ C) {
    __shared__ __align__(16) __nv_bfloat16 Ah[128 * ASTRIDE];
    __shared__ __align__(16) __nv_bfloat16 Al[128 * ASTRIDE];
    __shared__ uint32_t BpH[128 * BSTRIDE];
    __shared__ uint32_t BpL[128 * BSTRIDE];

    const int tid = threadIdx.x;
    const int bm = blockIdx.x * 128;
    const int bn = blockIdx.y * 128;
    const int lane = tid & 31;
    const int wid = tid >> 5;
    const int wm = (wid >> 2) * 64;
    const int wn = (wid & 3) * 32;
    const int g  = lane >> 2;
    const int c  = lane & 3;
    const int c2 = c * 2;

    float acc[4][4][4];
#pragma unroll
    for (int i = 0; i < 4; i++)
#pragma unroll
        for (int j = 0; j < 4; j++)
#pragma unroll
            for (int t = 0; t < 4; t++) acc[i][j][t] = 0.f;

    const int arow = tid >> 1;
    const int alc  = (tid & 1) * 16;
    const int agr  = bm + arow;
    const int bln  = tid & 127;
    const int blk  = (tid >> 7) * 16;

    float pa[16];
    float pb[16];

    {
        if (agr < NN) {
            const float4* s = (const float4*)(A + agr * 256 + 0 + alc);
#pragma unroll
            for (int q = 0; q < 4; q++) { float4 v = s[q]; pa[q*4+0]=v.x; pa[q*4+1]=v.y; pa[q*4+2]=v.z; pa[q*4+3]=v.w; }
        } else {
#pragma unroll
            for (int q = 0; q < 16; q++) pa[q] = 0.f;
        }
#pragma unroll
        for (int j = 0; j < 16; j++) pb[j] = B[(0 + blk + j) * 256 + bn + bln];
    }

    for (int kk = 0; kk < 256; kk += 32) {
        {
            uint32_t packedH[8], packedL[8];
#pragma unroll
            for (int t = 0; t < 8; t++) {
                __nv_bfloat16 h0, l0, h1, l1;
                split_bf16(pa[2*t],   h0, l0);
                split_bf16(pa[2*t+1], h1, l1);
                __nv_bfloat162 ph = {h0, h1}, pl = {l0, l1};
                packedH[t] = *(uint32_t*)&ph;
                packedL[t] = *(uint32_t*)&pl;
            }
            uint32_t* dstH = (uint32_t*)&Ah[arow * ASTRIDE + alc];
            uint32_t* dstL = (uint32_t*)&Al[arow * ASTRIDE + alc];
            *(uint4*)(dstH)     = make_uint4(packedH[0], packedH[1], packedH[2], packedH[3]);
            *(uint4*)(dstH + 4) = make_uint4(packedH[4], packedH[5], packedH[6], packedH[7]);
            *(uint4*)(dstL)     = make_uint4(packedL[0], packedL[1], packedL[2], packedL[3]);
            *(uint4*)(dstL + 4) = make_uint4(packedL[4], packedL[5], packedL[6], packedL[7]);
        }
        {
            const int base = bln * BSTRIDE + (blk >> 1);
#pragma unroll
            for (int t = 0; t < 8; t++) {
                __nv_bfloat16 h0, l0, h1, l1;
                split_bf16(pb[2*t],   h0, l0);
                split_bf16(pb[2*t+1], h1, l1);
                __nv_bfloat162 ph = {h0, h1}, pl = {l0, l1};
                BpH[base + t] = *(uint32_t*)&ph;
                BpL[base + t] = *(uint32_t*)&pl;
            }
        }
        __syncthreads();

        if (kk + 32 < 256) {
            if (agr < NN) {
                const float4* s = (const float4*)(A + agr * 256 + kk + 32 + alc);
#pragma unroll
                for (int q = 0; q < 4; q++) { float4 v = s[q]; pa[q*4+0]=v.x; pa[q*4+1]=v.y; pa[q*4+2]=v.z; pa[q*4+3]=v.w; }
            }
#pragma unroll
            for (int j = 0; j < 16; j++) pb[j] = B[(kk + 32 + blk + j) * 256 + bn + bln];
        }

#pragma unroll
        for (int ks = 0; ks < 2; ks++) {
            const int ko = ks * 16;
            const int k2 = ks * 8;
            uint32_t bh[4][2], bl[4][2];
#pragma unroll
            for (int j = 0; j < 4; j++) {
                int n = wn + j * 8 + g;
                bh[j][0] = BpH[n * BSTRIDE + k2 + c];
                bh[j][1] = BpH[n * BSTRIDE + k2 + c + 4];
                bl[j][0] = BpL[n * BSTRIDE + k2 + c];
                bl[j][1] = BpL[n * BSTRIDE + k2 + c + 4];
            }
#pragma unroll
            for (int i = 0; i < 4; i++) {
                const int r0 = wm + i * 16 + g;
                uint32_t ah[4], al_[4];
                ah[0]  = *(const uint32_t*)&Ah[r0 * ASTRIDE + ko + c2];
                ah[1]  = *(const uint32_t*)&Ah[(r0 + 8) * ASTRIDE + ko + c2];
                ah[2]  = *(const uint32_t*)&Ah[r0 * ASTRIDE + ko + c2 + 8];
                ah[3]  = *(const uint32_t*)&Ah[(r0 + 8) * ASTRIDE + ko + c2 + 8];
                al_[0] = *(const uint32_t*)&Al[r0 * ASTRIDE + ko + c2];
                al_[1] = *(const uint32_t*)&Al[(r0 + 8) * ASTRIDE + ko + c2];
                al_[2] = *(const uint32_t*)&Al[r0 * ASTRIDE + ko + c2 + 8];
                al_[3] = *(const uint32_t*)&Al[(r0 + 8) * ASTRIDE + ko + c2 + 8];
#pragma unroll
                for (int j = 0; j < 4; j++) {
                    mma16816(acc[i][j], ah, bh[j]);
                    mma16816(acc[i][j], ah, bl[j]);
                    mma16816(acc[i][j], al_, bh[j]);
                }
            }
        }
        __syncthreads();
    }

#pragma unroll
    for (int i = 0; i < 4; i++) {
        const int r = bm + wm + i * 16 + g;
#pragma unroll
        for (int j = 0; j < 4; j++) {
            const int col = bn + wn + j * 8 + c2;
            if (r < NN)
                *(float2*)(C + r * 256 + col) = make_float2(acc[i][j][0], acc[i][j][1]);
            if (r + 8 < NN)
                *(float2*)(C + (r + 8) * 256 + col) = make_float2(acc[i][j][2], acc[i][j][3]);
        }
    }
}

// ---------------- per-node prep: el/er -----------------------------------------
__global__ __launch_bounds__(256) void node_prep_kernel(const float* __restrict__ al,
                                                        const float* __restrict__ ar) {
    int warp = (blockIdx.x * blockDim.x + threadIdx.x) >> 5;
    int lane = threadIdx.x & 31;
    if (warp >= NN) return;

    const float4* f = (const float4*)(g_feat + warp * HD);
    float4 f0 = f[lane * 2], f1 = f[lane * 2 + 1];
    float4 a0 = ((const float4*)al)[lane * 2], a1 = ((const float4*)al)[lane * 2 + 1];
    float4 r0 = ((const float4*)ar)[lane * 2], r1 = ((const float4*)ar)[lane * 2 + 1];

    float pel = f0.x * a0.x + f0.y * a0.y + f0.z * a0.z + f0.w * a0.w +
                f1.x * a1.x + f1.y * a1.y + f1.z * a1.z + f1.w * a1.w;
    float per = f0.x * r0.x + f0.y * r0.y + f0.z * r0.z + f0.w * r0.w +
                f1.x * r1.x + f1.y * r1.y + f1.z * r1.z + f1.w * r1.w;
#pragma unroll
    for (int off = 4; off >= 1; off >>= 1) {
        pel += __shfl_down_sync(0xffffffffu, pel, off, 8);
        per += __shfl_down_sync(0xffffffffu, per, off, 8);
    }
    if ((lane & 7) == 0) {
        int h = lane >> 3;
        g_el[warp * HH + h] = pel;
        g_er[warp * HH + h] = per;
    }
}

// ---------------- fused edge softmax + aggregation + bias/relu ----------------
// One warp per node. Pass 1: per-head max over incoming edges. Pass 2:
// accumulate exp(e-m)*feat[src] and exp sums; normalize, +bias, relu, store.
template <bool LAST>
__global__ __launch_bounds__(256) void fused_edge_kernel(const float* __restrict__ b) {
    const int n = (blockIdx.x * blockDim.x + threadIdx.x) >> 5;
    const int lane = threadIdx.x & 31;
    if (n >= NN) return;

    const int off = g_off[n];
    const int deg = g_off[n + 1] - off;
    const int h = lane >> 3;

    const float4 er4 = *(const float4*)(g_er + n * HH);

    // ---- pass 1: per-head max ----
    float m0 = -CUDART_INF_F, m1 = -CUDART_INF_F, m2 = -CUDART_INF_F, m3 = -CUDART_INF_F;
    for (int i = lane; i < deg; i += 32) {
        int s = g_csr_src[off + i];
        float4 el4 = *(const float4*)(g_el + s * HH);
        float e0 = el4.x + er4.x; e0 = e0 > 0.f ? e0 : 0.2f * e0;
        float e1 = el4.y + er4.y; e1 = e1 > 0.f ? e1 : 0.2f * e1;
        float e2 = el4.z + er4.z; e2 = e2 > 0.f ? e2 : 0.2f * e2;
        float e3 = el4.w + er4.w; e3 = e3 > 0.f ? e3 : 0.2f * e3;
        m0 = fmaxf(m0, e0); m1 = fmaxf(m1, e1); m2 = fmaxf(m2, e2); m3 = fmaxf(m3, e3);
    }
#pragma unroll
    for (int o = 16; o >= 1; o >>= 1) {
        m0 = fmaxf(m0, __shfl_xor_sync(0xffffffffu, m0, o));
        m1 = fmaxf(m1, __shfl_xor_sync(0xffffffffu, m1, o));
        m2 = fmaxf(m2, __shfl_xor_sync(0xffffffffu, m2, o));
        m3 = fmaxf(m3, __shfl_xor_sync(0xffffffffu, m3, o));
    }
    const float mh  = (h == 0) ? m0 : (h == 1) ? m1 : (h == 2) ? m2 : m3;
    const float erh = (h == 0) ? er4.x : (h == 1) ? er4.y : (h == 2) ? er4.z : er4.w;

    // ---- pass 2: accumulate ----
    float acc[8];
#pragma unroll
    for (int j = 0; j < 8; j++) acc[j] = 0.f;
    float ssum = 0.f;

    for (int i = 0; i < deg; i++) {
        int s = g_csr_src[off + i];
        float e = g_el[s * HH + h] + erh;
        e = e > 0.f ? e : 0.2f * e;
        float a = __expf(e - mh);
        ssum += a;
        const float4* f = (const float4*)(g_feat + s * HD + lane * 8);
        float4 v0 = f[0], v1 = f[1];
        acc[0] += a * v0.x; acc[1] += a * v0.y; acc[2] += a * v0.z; acc[3] += a * v0.w;
        acc[4] += a * v1.x; acc[5] += a * v1.y; acc[6] += a * v1.z; acc[7] += a * v1.w;
    }
    const float inv = (ssum > 0.f) ? (1.f / ssum) : 0.f;

    const float4 b0 = *(const float4*)(b + lane * 8);
    const float4 b1 = *(const float4*)(b + lane * 8 + 4);
    float o0 = fmaxf(acc[0] * inv + b0.x, 0.f);
    float o1 = fmaxf(acc[1] * inv + b0.y, 0.f);
    float o2 = fmaxf(acc[2] * inv + b0.z, 0.f);
    float o3 = fmaxf(acc[3] * inv + b0.w, 0.f);
    float o4 = fmaxf(acc[4] * inv + b1.x, 0.f);
    float o5 = fmaxf(acc[5] * inv + b1.y, 0.f);
    float o6 = fmaxf(acc[6] * inv + b1.z, 0.f);
    float o7 = fmaxf(acc[7] * inv + b1.w, 0.f);

    if (LAST) {
        __half2 p0 = __floats2half2_rn(o0, o1);
        __half2 p1 = __floats2half2_rn(o2, o3);
        __half2 p2 = __floats2half2_rn(o4, o5);
        __half2 p3 = __floats2half2_rn(o6, o7);
        uint4 pk;
        pk.x = *(uint32_t*)&p0; pk.y = *(uint32_t*)&p1;
        pk.z = *(uint32_t*)&p2; pk.w = *(uint32_t*)&p3;
        ((uint4*)(g_hh + n * HD))[lane] = pk;
    } else {
        float4* o = (float4*)(g_h + n * HD + lane * 8);
        o[0] = make_float4(o0, o1, o2, o3);
        o[1] = make_float4(o4, o5, o6, o7);
    }
}

// ---------------- final dot scores (fp16 gather, fp32 accumulate) --------------
__global__ __launch_bounds__(256) void score_kernel(const int* __restrict__ src,
                                                    const int* __restrict__ dst,
                                                    const int* __restrict__ nsrc,
                                                    const int* __restrict__ ndst,
                                                    float* __restrict__ out) {
    int w = (blockIdx.x * blockDim.x + threadIdx.x) >> 5;
    int lane = threadIdx.x & 31;
    if (w >= 2 * EE) return;
    bool pos = w < EE;
    int e = pos ? w : w - EE;
    int uN = pos ? src[e] : nsrc[e];
    int vN = pos ? dst[e] : ndst[e];

    uint4 up = ((const uint4*)(g_hh + uN * HD))[lane];
    uint4 vp = ((const uint4*)(g_hh + vN * HD))[lane];
    float2 u0 = __half22float2(*(__half2*)&up.x), v0 = __half22float2(*(__half2*)&vp.x);
    float2 u1 = __half22float2(*(__half2*)&up.y), v1 = __half22float2(*(__half2*)&vp.y);
    float2 u2 = __half22float2(*(__half2*)&up.z), v2 = __half22float2(*(__half2*)&vp.z);
    float2 u3 = __half22float2(*(__half2*)&up.w), v3 = __half22float2(*(__half2*)&vp.w);
    float d = u0.x * v0.x + u0.y * v0.y + u1.x * v1.x + u1.y * v1.y +
              u2.x * v2.x + u2.y * v2.y + u3.x * v3.x + u3.y * v3.y;
#pragma unroll
    for (int off = 4; off >= 1; off >>= 1) d += __shfl_down_sync(0xffffffffu, d, off, 8);
    if ((lane & 7) == 0) {
        int h = lane >> 3;
        out[(pos ? 0 : EE * HH) + e * HH + h] = d;
    }
}

// ---------------- launch -------------------------------------------------------
extern "C" void kernel_launch(void* const* d_in, const int* in_sizes, int n_in,
                              void* d_out, int out_size) {
    const float* x    = (const float*)d_in[0];
    const int* src    = (const int*)d_in[1];
    const int* dst    = (const int*)d_in[2];
    const int* nsrc   = (const int*)d_in[3];
    const int* ndst   = (const int*)d_in[4];
    const float* W[3]  = {(const float*)d_in[5], (const float*)d_in[9],  (const float*)d_in[13]};
    const float* al[3] = {(const float*)d_in[6], (const float*)d_in[10], (const float*)d_in[14]};
    const float* ar[3] = {(const float*)d_in[7], (const float*)d_in[11], (const float*)d_in[15]};
    const float* bb[3] = {(const float*)d_in[8], (const float*)d_in[12], (const float*)d_in[16]};
    float* out = (float*)d_out;

    float* hbuf = nullptr;
    cudaGetSymbolAddress((void**)&hbuf, g_h);
    float* featbuf = nullptr;
    cudaGetSymbolAddress((void**)&featbuf, g_feat);

    // --- CSR build (dst constant across layers) ---
    csr_zero_kernel<<<(NN + 255) / 256, 256>>>();
    csr_hist_kernel<<<(EE + 255) / 256, 256>>>(dst);
    csr_scan_kernel<<<1, 1024>>>();
    csr_scatter_kernel<<<(EE + 255) / 256, 256>>>(src, dst);

    dim3 gemm_grid((NN + 127) / 128, 2);
    const int nprep_blocks = (NN * 32 + 255) / 256;
    const int node_blocks  = (NN * 32 + 255) / 256;
    const int score_blocks = (2 * EE * 32 + 255) / 256;

    const float* layer_in = x;
    for (int l = 0; l < 3; l++) {
        gemm_bf16x3<<<gemm_grid, 256>>>(layer_in, W[l], featbuf);
        node_prep_kernel<<<nprep_blocks, 256>>>(al[l], ar[l]);
        if (l == 2)
            fused_edge_kernel<true><<<node_blocks, 256>>>(bb[l]);
        else
            fused_edge_kernel<false><<<node_blocks, 256>>>(bb[l]);
        layer_in = hbuf;
    }
    score_kernel<<<score_blocks, 256>>>(src, dst, nsrc, ndst, out);
}

// round 4
// speedup vs baseline: 2.2479x; 1.1285x over previous
#include <cuda_runtime.h>
#include <cuda_bf16.h>
#include <cuda_fp16.h>
#include <math_constants.h>
#include <stdint.h>

#define NN 25000
#define EE 250000
#define HH 4
#define DD 64
#define HD 256   // H*D

// ---------------- scratch (device globals; no allocation allowed) -------------
__device__ __half g_feat16[NN * HD];   // x @ W for current layer, fp16
__device__ float  g_h[NN * HD];        // layer output (next layer input), fp32
__device__ __half g_hh[NN * HD];       // final layer output, fp16 (score input)
// el/er partials: two deterministic contribution slots per (node, head)
__device__ float g_elp[2 * NN * HH];
__device__ float g_erp[2 * NN * HH];
// CSR by dst (built once per launch; dst identical across layers)
__device__ int g_cnt[NN];
__device__ int g_off[NN + 1];
__device__ int g_cur[NN];
__device__ int g_csr_src[EE];

// ---------------- helpers ----------------------------------------------------
__device__ __forceinline__ void mma16816(float* d, const uint32_t* a, const uint32_t* b) {
    asm volatile(
        "mma.sync.aligned.m16n8k16.row.col.f32.bf16.bf16.f32 "
        "{%0,%1,%2,%3}, {%4,%5,%6,%7}, {%8,%9}, {%0,%1,%2,%3};"
        : "+f"(d[0]), "+f"(d[1]), "+f"(d[2]), "+f"(d[3])
        : "r"(a[0]), "r"(a[1]), "r"(a[2]), "r"(a[3]), "r"(b[0]), "r"(b[1]));
}

__device__ __forceinline__ void split_bf16(float f, __nv_bfloat16& h, __nv_bfloat16& l) {
    h = __float2bfloat16(f);
    l = __float2bfloat16(f - __bfloat162float(h));
}

// ---------------- CSR build ---------------------------------------------------
__global__ __launch_bounds__(256) void csr_hist_kernel(const int* __restrict__ dst) {
    int i = blockIdx.x * blockDim.x + threadIdx.x;
    if (i < EE) atomicAdd(&g_cnt[dst[i]], 1);
}

// single block, 1024 threads; each thread owns 25 consecutive nodes
__global__ __launch_bounds__(1024) void csr_scan_kernel() {
    __shared__ int part[1024];
    const int tid = threadIdx.x;
    const int base = tid * 25;
    int loc[25];
    int s = 0;
#pragma unroll
    for (int j = 0; j < 25; j++) {
        int idx = base + j;
        int c = (idx < NN) ? g_cnt[idx] : 0;
        loc[j] = s;
        s += c;
    }
    part[tid] = s;
    __syncthreads();
    for (int off = 1; off < 1024; off <<= 1) {
        int v = (tid >= off) ? part[tid - off] : 0;
        __syncthreads();
        part[tid] += v;
        __syncthreads();
    }
    const int excl = (tid == 0) ? 0 : part[tid - 1];
#pragma unroll
    for (int j = 0; j < 25; j++) {
        int idx = base + j;
        if (idx < NN) {
            int o = excl + loc[j];
            g_off[idx] = o;
            g_cur[idx] = o;
        }
    }
    if (tid == 0) g_off[NN] = EE;
}

__global__ __launch_bounds__(256) void csr_scatter_kernel(const int* __restrict__ src,
                                                          const int* __restrict__ dst) {
    int e = blockIdx.x * blockDim.x + threadIdx.x;
    if (e >= EE) return;
    int slot = atomicAdd(&g_cur[dst[e]], 1);
    g_csr_src[slot] = src[e];
}

// ---------------- GEMM (bf16-split tensor cores) + fused el/er + fp16 out -----
// C16[M,256] = fp16(A[M,256] @ B[256,256]);  el/er partials per (node, head)
// written to deterministic slots (no atomics). Block 128x128, BK=32, 8 warps.
#define ASTRIDE 40
#define BSTRIDE 17

__global__ __launch_bounds__(256) void gemm_fused(const float* __restrict__ A,
                                                  const float* __restrict__ B,
                                                  const float* __restrict__ alp,
                                                  const float* __restrict__ arp,
                                                  __half* __restrict__ C16) {
    __shared__ __align__(16) __nv_bfloat16 Ah[128 * ASTRIDE];
    __shared__ __align__(16) __nv_bfloat16 Al[128 * ASTRIDE];
    __shared__ uint32_t BpH[128 * BSTRIDE];
    __shared__ uint32_t BpL[128 * BSTRIDE];

    const int tid = threadIdx.x;
    const int bm = blockIdx.x * 128;
    const int bn = blockIdx.y * 128;
    const int lane = tid & 31;
    const int wid = tid >> 5;
    const int wm = (wid >> 2) * 64;
    const int wn = (wid & 3) * 32;
    const int g  = lane >> 2;
    const int c  = lane & 3;
    const int c2 = c * 2;

    float acc[4][4][4];
#pragma unroll
    for (int i = 0; i < 4; i++)
#pragma unroll
        for (int j = 0; j < 4; j++)
#pragma unroll
            for (int t = 0; t < 4; t++) acc[i][j][t] = 0.f;

    const int arow = tid >> 1;
    const int alc  = (tid & 1) * 16;
    const int agr  = bm + arow;
    const int bln  = tid & 127;
    const int blk  = (tid >> 7) * 16;

    float pa[16];
    float pb[16];

    {
        if (agr < NN) {
            const float4* s = (const float4*)(A + agr * 256 + 0 + alc);
#pragma unroll
            for (int q = 0; q < 4; q++) { float4 v = s[q]; pa[q*4+0]=v.x; pa[q*4+1]=v.y; pa[q*4+2]=v.z; pa[q*4+3]=v.w; }
        } else {
#pragma unroll
            for (int q = 0; q < 16; q++) pa[q] = 0.f;
        }
#pragma unroll
        for (int j = 0; j < 16; j++) pb[j] = B[(0 + blk + j) * 256 + bn + bln];
    }

    for (int kk = 0; kk < 256; kk += 32) {
        {
            uint32_t packedH[8], packedL[8];
#pragma unroll
            for (int t = 0; t < 8; t++) {
                __nv_bfloat16 h0, l0, h1, l1;
                split_bf16(pa[2*t],   h0, l0);
                split_bf16(pa[2*t+1], h1, l1);
                __nv_bfloat162 ph = {h0, h1}, pl = {l0, l1};
                packedH[t] = *(uint32_t*)&ph;
                packedL[t] = *(uint32_t*)&pl;
            }
            uint32_t* dstH = (uint32_t*)&Ah[arow * ASTRIDE + alc];
            uint32_t* dstL = (uint32_t*)&Al[arow * ASTRIDE + alc];
            *(uint4*)(dstH)     = make_uint4(packedH[0], packedH[1], packedH[2], packedH[3]);
            *(uint4*)(dstH + 4) = make_uint4(packedH[4], packedH[5], packedH[6], packedH[7]);
            *(uint4*)(dstL)     = make_uint4(packedL[0], packedL[1], packedL[2], packedL[3]);
            *(uint4*)(dstL + 4) = make_uint4(packedL[4], packedL[5], packedL[6], packedL[7]);
        }
        {
            const int base = bln * BSTRIDE + (blk >> 1);
#pragma unroll
            for (int t = 0; t < 8; t++) {
                __nv_bfloat16 h0, l0, h1, l1;
                split_bf16(pb[2*t],   h0, l0);
                split_bf16(pb[2*t+1], h1, l1);
                __nv_bfloat162 ph = {h0, h1}, pl = {l0, l1};
                BpH[base + t] = *(uint32_t*)&ph;
                BpL[base + t] = *(uint32_t*)&pl;
            }
        }
        __syncthreads();

        if (kk + 32 < 256) {
            if (agr < NN) {
                const float4* s = (const float4*)(A + agr * 256 + kk + 32 + alc);
#pragma unroll
                for (int q = 0; q < 4; q++) { float4 v = s[q]; pa[q*4+0]=v.x; pa[q*4+1]=v.y; pa[q*4+2]=v.z; pa[q*4+3]=v.w; }
            }
#pragma unroll
            for (int j = 0; j < 16; j++) pb[j] = B[(kk + 32 + blk + j) * 256 + bn + bln];
        }

#pragma unroll
        for (int ks = 0; ks < 2; ks++) {
            const int ko = ks * 16;
            const int k2 = ks * 8;
            uint32_t bh[4][2], bl[4][2];
#pragma unroll
            for (int j = 0; j < 4; j++) {
                int n = wn + j * 8 + g;
                bh[j][0] = BpH[n * BSTRIDE + k2 + c];
                bh[j][1] = BpH[n * BSTRIDE + k2 + c + 4];
                bl[j][0] = BpL[n * BSTRIDE + k2 + c];
                bl[j][1] = BpL[n * BSTRIDE + k2 + c + 4];
            }
#pragma unroll
            for (int i = 0; i < 4; i++) {
                const int r0 = wm + i * 16 + g;
                uint32_t ah[4], al_[4];
                ah[0]  = *(const uint32_t*)&Ah[r0 * ASTRIDE + ko + c2];
                ah[1]  = *(const uint32_t*)&Ah[(r0 + 8) * ASTRIDE + ko + c2];
                ah[2]  = *(const uint32_t*)&Ah[r0 * ASTRIDE + ko + c2 + 8];
                ah[3]  = *(const uint32_t*)&Ah[(r0 + 8) * ASTRIDE + ko + c2 + 8];
                al_[0] = *(const uint32_t*)&Al[r0 * ASTRIDE + ko + c2];
                al_[1] = *(const uint32_t*)&Al[(r0 + 8) * ASTRIDE + ko + c2];
                al_[2] = *(const uint32_t*)&Al[r0 * ASTRIDE + ko + c2 + 8];
                al_[3] = *(const uint32_t*)&Al[(r0 + 8) * ASTRIDE + ko + c2 + 8];
#pragma unroll
                for (int j = 0; j < 4; j++) {
                    mma16816(acc[i][j], ah, bh[j]);
                    mma16816(acc[i][j], ah, bl[j]);
                    mma16816(acc[i][j], al_, bh[j]);
                }
            }
        }
        __syncthreads();
    }

    // ---- epilogue: fp16 feat store + fused el/er partials ----
    // This warp's 32 columns lie within one head; slot q = which half of the head.
    const int colbase = bn + wn;
    const int hh_ = colbase >> 6;
    const int q_  = (colbase >> 5) & 1;
    float alv[4][2], arv[4][2];
#pragma unroll
    for (int j = 0; j < 4; j++) {
        int col = colbase + j * 8 + c2;
        alv[j][0] = alp[col];     alv[j][1] = alp[col + 1];
        arv[j][0] = arp[col];     arv[j][1] = arp[col + 1];
    }

#pragma unroll
    for (int i = 0; i < 4; i++) {
        const int r = bm + wm + i * 16 + g;
        float pel0 = 0.f, per0 = 0.f, pel1 = 0.f, per1 = 0.f;
#pragma unroll
        for (int j = 0; j < 4; j++) {
            const int col = colbase + j * 8 + c2;
            pel0 += acc[i][j][0] * alv[j][0] + acc[i][j][1] * alv[j][1];
            per0 += acc[i][j][0] * arv[j][0] + acc[i][j][1] * arv[j][1];
            pel1 += acc[i][j][2] * alv[j][0] + acc[i][j][3] * alv[j][1];
            per1 += acc[i][j][2] * arv[j][0] + acc[i][j][3] * arv[j][1];
            // fp16 feat stores
            __half2 h01 = __floats2half2_rn(acc[i][j][0], acc[i][j][1]);
            __half2 h23 = __floats2half2_rn(acc[i][j][2], acc[i][j][3]);
            if (r < NN)     *(__half2*)(C16 + r * 256 + col)       = h01;
            if (r + 8 < NN) *(__half2*)(C16 + (r + 8) * 256 + col) = h23;
        }
        // reduce over the c-quad (lanes differing in bits 0-1)
#pragma unroll
        for (int o = 1; o <= 2; o <<= 1) {
            pel0 += __shfl_xor_sync(0xffffffffu, pel0, o);
            per0 += __shfl_xor_sync(0xffffffffu, per0, o);
            pel1 += __shfl_xor_sync(0xffffffffu, pel1, o);
            per1 += __shfl_xor_sync(0xffffffffu, per1, o);
        }
        if (c == 0) {
            if (r < NN) {
                g_elp[q_ * (NN * HH) + r * HH + hh_] = pel0;
                g_erp[q_ * (NN * HH) + r * HH + hh_] = per0;
            }
            if (r + 8 < NN) {
                g_elp[q_ * (NN * HH) + (r + 8) * HH + hh_] = pel1;
                g_erp[q_ * (NN * HH) + (r + 8) * HH + hh_] = per1;
            }
        }
    }
}

// ---------------- fused edge softmax + aggregation + bias/relu (single pass) --
// One warp per node. exp without max-shift (|e| bounded ~10 by construction;
// exp(e)/sum(exp(e)) is mathematically identical to the shifted form).
template <bool LAST>
__global__ __launch_bounds__(256) void fused_edge_kernel(const float* __restrict__ b) {
    const int n = (blockIdx.x * blockDim.x + threadIdx.x) >> 5;
    const int lane = threadIdx.x & 31;
    if (n >= NN) return;

    const int off = g_off[n];
    const int deg = g_off[n + 1] - off;
    const int h = lane >> 3;

    const float erh = g_erp[n * HH + h] + g_erp[NN * HH + n * HH + h];

    float acc[8];
#pragma unroll
    for (int j = 0; j < 8; j++) acc[j] = 0.f;
    float ssum = 0.f;

    for (int i = 0; i < deg; i++) {
        const int s = g_csr_src[off + i];
        float e = g_elp[s * HH + h] + g_elp[NN * HH + s * HH + h] + erh;
        e = e > 0.f ? e : 0.2f * e;
        const float a = __expf(e);
        ssum += a;
        const uint4 p = *(const uint4*)(g_feat16 + s * HD + lane * 8);
        const __half2* ph = (const __half2*)&p;
        float2 f0 = __half22float2(ph[0]);
        float2 f1 = __half22float2(ph[1]);
        float2 f2 = __half22float2(ph[2]);
        float2 f3 = __half22float2(ph[3]);
        acc[0] += a * f0.x; acc[1] += a * f0.y;
        acc[2] += a * f1.x; acc[3] += a * f1.y;
        acc[4] += a * f2.x; acc[5] += a * f2.y;
        acc[6] += a * f3.x; acc[7] += a * f3.y;
    }
    const float inv = (ssum > 0.f) ? (1.f / ssum) : 0.f;

    const float4 b0 = *(const float4*)(b + lane * 8);
    const float4 b1 = *(const float4*)(b + lane * 8 + 4);
    float o0 = fmaxf(acc[0] * inv + b0.x, 0.f);
    float o1 = fmaxf(acc[1] * inv + b0.y, 0.f);
    float o2 = fmaxf(acc[2] * inv + b0.z, 0.f);
    float o3 = fmaxf(acc[3] * inv + b0.w, 0.f);
    float o4 = fmaxf(acc[4] * inv + b1.x, 0.f);
    float o5 = fmaxf(acc[5] * inv + b1.y, 0.f);
    float o6 = fmaxf(acc[6] * inv + b1.z, 0.f);
    float o7 = fmaxf(acc[7] * inv + b1.w, 0.f);

    if (LAST) {
        __half2 p0 = __floats2half2_rn(o0, o1);
        __half2 p1 = __floats2half2_rn(o2, o3);
        __half2 p2 = __floats2half2_rn(o4, o5);
        __half2 p3 = __floats2half2_rn(o6, o7);
        uint4 pk;
        pk.x = *(uint32_t*)&p0; pk.y = *(uint32_t*)&p1;
        pk.z = *(uint32_t*)&p2; pk.w = *(uint32_t*)&p3;
        ((uint4*)(g_hh + n * HD))[lane] = pk;
    } else {
        float4* o = (float4*)(g_h + n * HD + lane * 8);
        o[0] = make_float4(o0, o1, o2, o3);
        o[1] = make_float4(o4, o5, o6, o7);
    }
}

// ---------------- final dot scores (fp16 gather, fp32 accumulate) --------------
__global__ __launch_bounds__(256) void score_kernel(const int* __restrict__ src,
                                                    const int* __restrict__ dst,
                                                    const int* __restrict__ nsrc,
                                                    const int* __restrict__ ndst,
                                                    float* __restrict__ out) {
    int w = (blockIdx.x * blockDim.x + threadIdx.x) >> 5;
    int lane = threadIdx.x & 31;
    if (w >= 2 * EE) return;
    bool pos = w < EE;
    int e = pos ? w : w - EE;
    int uN = pos ? src[e] : nsrc[e];
    int vN = pos ? dst[e] : ndst[e];

    uint4 up = ((const uint4*)(g_hh + uN * HD))[lane];
    uint4 vp = ((const uint4*)(g_hh + vN * HD))[lane];
    float2 u0 = __half22float2(*(__half2*)&up.x), v0 = __half22float2(*(__half2*)&vp.x);
    float2 u1 = __half22float2(*(__half2*)&up.y), v1 = __half22float2(*(__half2*)&vp.y);
    float2 u2 = __half22float2(*(__half2*)&up.z), v2 = __half22float2(*(__half2*)&vp.z);
    float2 u3 = __half22float2(*(__half2*)&up.w), v3 = __half22float2(*(__half2*)&vp.w);
    float d = u0.x * v0.x + u0.y * v0.y + u1.x * v1.x + u1.y * v1.y +
              u2.x * v2.x + u2.y * v2.y + u3.x * v3.x + u3.y * v3.y;
#pragma unroll
    for (int off = 4; off >= 1; off >>= 1) d += __shfl_down_sync(0xffffffffu, d, off, 8);
    if ((lane & 7) == 0) {
        int h = lane >> 3;
        out[(pos ? 0 : EE * HH) + e * HH + h] = d;
    }
}

// ---------------- launch -------------------------------------------------------
extern "C" void kernel_launch(void* const* d_in, const int* in_sizes, int n_in,
                              void* d_out, int out_size) {
    const float* x    = (const float*)d_in[0];
    const int* src    = (const int*)d_in[1];
    const int* dst    = (const int*)d_in[2];
    const int* nsrc   = (const int*)d_in[3];
    const int* ndst   = (const int*)d_in[4];
    const float* W[3]  = {(const float*)d_in[5], (const float*)d_in[9],  (const float*)d_in[13]};
    const float* al[3] = {(const float*)d_in[6], (const float*)d_in[10], (const float*)d_in[14]};
    const float* ar[3] = {(const float*)d_in[7], (const float*)d_in[11], (const float*)d_in[15]};
    const float* bb[3] = {(const float*)d_in[8], (const float*)d_in[12], (const float*)d_in[16]};
    float* out = (float*)d_out;

    float* hbuf = nullptr;
    cudaGetSymbolAddress((void**)&hbuf, g_h);
    __half* featbuf = nullptr;
    cudaGetSymbolAddress((void**)&featbuf, g_feat16);
    int* cntbuf = nullptr;
    cudaGetSymbolAddress((void**)&cntbuf, g_cnt);

    // --- CSR build (dst constant across layers) ---
    cudaMemsetAsync(cntbuf, 0, NN * sizeof(int));
    csr_hist_kernel<<<(EE + 255) / 256, 256>>>(dst);
    csr_scan_kernel<<<1, 1024>>>();
    csr_scatter_kernel<<<(EE + 255) / 256, 256>>>(src, dst);

    dim3 gemm_grid((NN + 127) / 128, 2);
    const int node_blocks  = (NN * 32 + 255) / 256;
    const int score_blocks = (2 * EE * 32 + 255) / 256;

    const float* layer_in = x;
    for (int l = 0; l < 3; l++) {
        gemm_fused<<<gemm_grid, 256>>>(layer_in, W[l], al[l], ar[l], featbuf);
        if (l == 2)
            fused_edge_kernel<true><<<node_blocks, 256>>>(bb[l]);
        else
            fused_edge_kernel<false><<<node_blocks, 256>>>(bb[l]);
        layer_in = hbuf;
    }
    score_kernel<<<score_blocks, 256>>>(src, dst, nsrc, ndst, out);
}

// round 5
// speedup vs baseline: 2.4898x; 1.1076x over previous
#include <cuda_runtime.h>
#include <cuda_bf16.h>
#include <cuda_fp16.h>
#include <math_constants.h>
#include <stdint.h>

#define NN 25000
#define EE 250000
#define HH 4
#define DD 64
#define HD 256   // H*D

// ---------------- scratch (device globals; no allocation allowed) -------------
__device__ __half g_feat16[NN * HD];   // x @ W for current layer, fp16
__device__ float  g_h[NN * HD];        // layer output (next layer input), fp32
__device__ __half g_hh[NN * HD];       // final layer output, fp16 (score input)
// el/er partials: two deterministic contribution slots per (node, head)
__device__ float g_elp[2 * NN * HH];
__device__ float g_erp[2 * NN * HH];
// CSR by dst (built once per launch; dst identical across layers)
__device__ int g_cnt[NN];
__device__ int g_off[NN + 1];
__device__ int g_cur[NN];
__device__ int g_csr_src[EE];

// ---------------- helpers ----------------------------------------------------
__device__ __forceinline__ void mma_tf32(float* d, const uint32_t* a, const uint32_t* b) {
    asm volatile(
        "mma.sync.aligned.m16n8k8.row.col.f32.tf32.tf32.f32 "
        "{%0,%1,%2,%3}, {%4,%5,%6,%7}, {%8,%9}, {%0,%1,%2,%3};"
        : "+f"(d[0]), "+f"(d[1]), "+f"(d[2]), "+f"(d[3])
        : "r"(a[0]), "r"(a[1]), "r"(a[2]), "r"(a[3]), "r"(b[0]), "r"(b[1]));
}

// round-to-nearest tf32 (unbiased; raw truncation would bias dots by ~5e-4)
__device__ __forceinline__ uint32_t f2tf32(float f) {
    uint32_t r;
    asm("cvt.rna.tf32.f32 %0, %1;" : "=r"(r) : "f"(f));
    return r;
}

// ---------------- CSR build ---------------------------------------------------
__global__ __launch_bounds__(256) void csr_hist_kernel(const int* __restrict__ dst) {
    int i = blockIdx.x * blockDim.x + threadIdx.x;
    if (i < EE) atomicAdd(&g_cnt[dst[i]], 1);
}

__global__ __launch_bounds__(1024) void csr_scan_kernel() {
    __shared__ int part[1024];
    const int tid = threadIdx.x;
    const int base = tid * 25;
    int loc[25];
    int s = 0;
#pragma unroll
    for (int j = 0; j < 25; j++) {
        int idx = base + j;
        int c = (idx < NN) ? g_cnt[idx] : 0;
        loc[j] = s;
        s += c;
    }
    part[tid] = s;
    __syncthreads();
    for (int off = 1; off < 1024; off <<= 1) {
        int v = (tid >= off) ? part[tid - off] : 0;
        __syncthreads();
        part[tid] += v;
        __syncthreads();
    }
    const int excl = (tid == 0) ? 0 : part[tid - 1];
#pragma unroll
    for (int j = 0; j < 25; j++) {
        int idx = base + j;
        if (idx < NN) {
            int o = excl + loc[j];
            g_off[idx] = o;
            g_cur[idx] = o;
        }
    }
    if (tid == 0) g_off[NN] = EE;
}

__global__ __launch_bounds__(256) void csr_scatter_kernel(const int* __restrict__ src,
                                                          const int* __restrict__ dst) {
    int e = blockIdx.x * blockDim.x + threadIdx.x;
    if (e >= EE) return;
    int slot = atomicAdd(&g_cur[dst[e]], 1);
    g_csr_src[slot] = src[e];
}

// ---------------- TF32 GEMM + fused el/er + fp16 out --------------------------
// C16[M,256] = fp16(A[M,256] @ B[256,256]) via single-pass tf32 mma (rna cvt).
// Block 128x128, BK=16, 8 warps (2m x 4n), warp tile 64x32 (4x4 m16n8 atoms).
// A smem stride 20 floats: frag banks (20g+c) all-distinct. B smem stride 136:
// frag banks (8c+g) all-distinct. Register prefetch single-buffer pipeline.
#define ASTRIDE 20
#define BSTRIDE 136

__global__ __launch_bounds__(256, 2) void gemm_fused(const float* __restrict__ A,
                                                     const float* __restrict__ B,
                                                     const float* __restrict__ alp,
                                                     const float* __restrict__ arp,
                                                     __half* __restrict__ C16) {
    __shared__ __align__(16) uint32_t As[128 * ASTRIDE];
    __shared__ __align__(16) uint32_t Bs[16 * BSTRIDE];

    const int tid = threadIdx.x;
    const int bm = blockIdx.x * 128;
    const int bn = blockIdx.y * 128;
    const int lane = tid & 31;
    const int wid = tid >> 5;
    const int wm = (wid >> 2) * 64;
    const int wn = (wid & 3) * 32;
    const int g  = lane >> 2;
    const int c  = lane & 3;
    const int c2 = c * 2;

    float acc[4][4][4];
#pragma unroll
    for (int i = 0; i < 4; i++)
#pragma unroll
        for (int j = 0; j < 4; j++)
#pragma unroll
            for (int t = 0; t < 4; t++) acc[i][j][t] = 0.f;

    // A loader: thread -> row tid>>1 (0..127), k-offset (tid&1)*8, 8 floats
    const int arow = tid >> 1;
    const int ak   = (tid & 1) * 8;
    const int agr  = bm + arow;
    const bool aval = agr < NN;
    // B loader: thread -> k = tid>>4 (0..15), n0 = (tid&15)*8, 8 floats
    const int bk  = tid >> 4;
    const int bn0 = (tid & 15) * 8;

    float pa[8], pb[8];

    // prefetch stage 0
    {
        if (aval) {
            const float4* s = (const float4*)(A + agr * 256 + ak);
            float4 v0 = s[0], v1 = s[1];
            pa[0]=v0.x; pa[1]=v0.y; pa[2]=v0.z; pa[3]=v0.w;
            pa[4]=v1.x; pa[5]=v1.y; pa[6]=v1.z; pa[7]=v1.w;
        } else {
#pragma unroll
            for (int q = 0; q < 8; q++) pa[q] = 0.f;
        }
        const float4* s = (const float4*)(B + bk * 256 + bn + bn0);
        float4 v0 = s[0], v1 = s[1];
        pb[0]=v0.x; pb[1]=v0.y; pb[2]=v0.z; pb[3]=v0.w;
        pb[4]=v1.x; pb[5]=v1.y; pb[6]=v1.z; pb[7]=v1.w;
    }

    for (int kk = 0; kk < 256; kk += 16) {
        // ---- store prefetched panel to shared (cvt to tf32) ----
        {
            uint32_t ta[8], tb[8];
#pragma unroll
            for (int q = 0; q < 8; q++) { ta[q] = f2tf32(pa[q]); tb[q] = f2tf32(pb[q]); }
            uint32_t* da = &As[arow * ASTRIDE + ak];
            *(uint4*)(da)     = make_uint4(ta[0], ta[1], ta[2], ta[3]);
            *(uint4*)(da + 4) = make_uint4(ta[4], ta[5], ta[6], ta[7]);
            uint32_t* db = &Bs[bk * BSTRIDE + bn0];
            *(uint4*)(db)     = make_uint4(tb[0], tb[1], tb[2], tb[3]);
            *(uint4*)(db + 4) = make_uint4(tb[4], tb[5], tb[6], tb[7]);
        }
        __syncthreads();

        // ---- prefetch next stage ----
        if (kk + 16 < 256) {
            if (aval) {
                const float4* s = (const float4*)(A + agr * 256 + kk + 16 + ak);
                float4 v0 = s[0], v1 = s[1];
                pa[0]=v0.x; pa[1]=v0.y; pa[2]=v0.z; pa[3]=v0.w;
                pa[4]=v1.x; pa[5]=v1.y; pa[6]=v1.z; pa[7]=v1.w;
            }
            const float4* s = (const float4*)(B + (kk + 16 + bk) * 256 + bn + bn0);
            float4 v0 = s[0], v1 = s[1];
            pb[0]=v0.x; pb[1]=v0.y; pb[2]=v0.z; pb[3]=v0.w;
            pb[4]=v1.x; pb[5]=v1.y; pb[6]=v1.z; pb[7]=v1.w;
        }

        // ---- compute: 2 x k8 steps ----
#pragma unroll
        for (int ks = 0; ks < 2; ks++) {
            const int kb = ks * 8;
            uint32_t bfr[4][2];
#pragma unroll
            for (int j = 0; j < 4; j++) {
                const int n = wn + j * 8 + g;
                bfr[j][0] = Bs[(kb + c) * BSTRIDE + n];
                bfr[j][1] = Bs[(kb + c + 4) * BSTRIDE + n];
            }
#pragma unroll
            for (int i = 0; i < 4; i++) {
                const int r0 = wm + i * 16 + g;
                uint32_t afr[4];
                afr[0] = As[r0 * ASTRIDE + kb + c];
                afr[1] = As[(r0 + 8) * ASTRIDE + kb + c];
                afr[2] = As[r0 * ASTRIDE + kb + c + 4];
                afr[3] = As[(r0 + 8) * ASTRIDE + kb + c + 4];
#pragma unroll
                for (int j = 0; j < 4; j++) mma_tf32(acc[i][j], afr, bfr[j]);
            }
        }
        __syncthreads();
    }

    // ---- epilogue: fp16 feat store + fused el/er partials ----
    const int colbase = bn + wn;
    const int hh_ = colbase >> 6;
    const int q_  = (colbase >> 5) & 1;
    float alv[4][2], arv[4][2];
#pragma unroll
    for (int j = 0; j < 4; j++) {
        int col = colbase + j * 8 + c2;
        alv[j][0] = alp[col];     alv[j][1] = alp[col + 1];
        arv[j][0] = arp[col];     arv[j][1] = arp[col + 1];
    }

#pragma unroll
    for (int i = 0; i < 4; i++) {
        const int r = bm + wm + i * 16 + g;
        float pel0 = 0.f, per0 = 0.f, pel1 = 0.f, per1 = 0.f;
#pragma unroll
        for (int j = 0; j < 4; j++) {
            const int col = colbase + j * 8 + c2;
            pel0 += acc[i][j][0] * alv[j][0] + acc[i][j][1] * alv[j][1];
            per0 += acc[i][j][0] * arv[j][0] + acc[i][j][1] * arv[j][1];
            pel1 += acc[i][j][2] * alv[j][0] + acc[i][j][3] * alv[j][1];
            per1 += acc[i][j][2] * arv[j][0] + acc[i][j][3] * arv[j][1];
            __half2 h01 = __floats2half2_rn(acc[i][j][0], acc[i][j][1]);
            __half2 h23 = __floats2half2_rn(acc[i][j][2], acc[i][j][3]);
            if (r < NN)     *(__half2*)(C16 + r * 256 + col)       = h01;
            if (r + 8 < NN) *(__half2*)(C16 + (r + 8) * 256 + col) = h23;
        }
#pragma unroll
        for (int o = 1; o <= 2; o <<= 1) {
            pel0 += __shfl_xor_sync(0xffffffffu, pel0, o);
            per0 += __shfl_xor_sync(0xffffffffu, per0, o);
            pel1 += __shfl_xor_sync(0xffffffffu, pel1, o);
            per1 += __shfl_xor_sync(0xffffffffu, per1, o);
        }
        if (c == 0) {
            if (r < NN) {
                g_elp[q_ * (NN * HH) + r * HH + hh_] = pel0;
                g_erp[q_ * (NN * HH) + r * HH + hh_] = per0;
            }
            if (r + 8 < NN) {
                g_elp[q_ * (NN * HH) + (r + 8) * HH + hh_] = pel1;
                g_erp[q_ * (NN * HH) + (r + 8) * HH + hh_] = per1;
            }
        }
    }
}

// ---------------- fused edge softmax + aggregation + bias/relu (single pass) --
template <bool LAST>
__global__ __launch_bounds__(256) void fused_edge_kernel(const float* __restrict__ b) {
    const int n = (blockIdx.x * blockDim.x + threadIdx.x) >> 5;
    const int lane = threadIdx.x & 31;
    if (n >= NN) return;

    const int off = g_off[n];
    const int deg = g_off[n + 1] - off;
    const int h = lane >> 3;

    const float erh = g_erp[n * HH + h] + g_erp[NN * HH + n * HH + h];

    float acc[8];
#pragma unroll
    for (int j = 0; j < 8; j++) acc[j] = 0.f;
    float ssum = 0.f;

    for (int i = 0; i < deg; i++) {
        const int s = g_csr_src[off + i];
        float e = g_elp[s * HH + h] + g_elp[NN * HH + s * HH + h] + erh;
        e = e > 0.f ? e : 0.2f * e;
        const float a = __expf(e);
        ssum += a;
        const uint4 p = *(const uint4*)(g_feat16 + s * HD + lane * 8);
        const __half2* ph = (const __half2*)&p;
        float2 f0 = __half22float2(ph[0]);
        float2 f1 = __half22float2(ph[1]);
        float2 f2 = __half22float2(ph[2]);
        float2 f3 = __half22float2(ph[3]);
        acc[0] += a * f0.x; acc[1] += a * f0.y;
        acc[2] += a * f1.x; acc[3] += a * f1.y;
        acc[4] += a * f2.x; acc[5] += a * f2.y;
        acc[6] += a * f3.x; acc[7] += a * f3.y;
    }
    const float inv = (ssum > 0.f) ? (1.f / ssum) : 0.f;

    const float4 b0 = *(const float4*)(b + lane * 8);
    const float4 b1 = *(const float4*)(b + lane * 8 + 4);
    float o0 = fmaxf(acc[0] * inv + b0.x, 0.f);
    float o1 = fmaxf(acc[1] * inv + b0.y, 0.f);
    float o2 = fmaxf(acc[2] * inv + b0.z, 0.f);
    float o3 = fmaxf(acc[3] * inv + b0.w, 0.f);
    float o4 = fmaxf(acc[4] * inv + b1.x, 0.f);
    float o5 = fmaxf(acc[5] * inv + b1.y, 0.f);
    float o6 = fmaxf(acc[6] * inv + b1.z, 0.f);
    float o7 = fmaxf(acc[7] * inv + b1.w, 0.f);

    if (LAST) {
        __half2 p0 = __floats2half2_rn(o0, o1);
        __half2 p1 = __floats2half2_rn(o2, o3);
        __half2 p2 = __floats2half2_rn(o4, o5);
        __half2 p3 = __floats2half2_rn(o6, o7);
        uint4 pk;
        pk.x = *(uint32_t*)&p0; pk.y = *(uint32_t*)&p1;
        pk.z = *(uint32_t*)&p2; pk.w = *(uint32_t*)&p3;
        ((uint4*)(g_hh + n * HD))[lane] = pk;
    } else {
        float4* o = (float4*)(g_h + n * HD + lane * 8);
        o[0] = make_float4(o0, o1, o2, o3);
        o[1] = make_float4(o4, o5, o6, o7);
    }
}

// ---------------- final dot scores (fp16 gather, fp32 accumulate) --------------
__global__ __launch_bounds__(256) void score_kernel(const int* __restrict__ src,
                                                    const int* __restrict__ dst,
                                                    const int* __restrict__ nsrc,
                                                    const int* __restrict__ ndst,
                                                    float* __restrict__ out) {
    int w = (blockIdx.x * blockDim.x + threadIdx.x) >> 5;
    int lane = threadIdx.x & 31;
    if (w >= 2 * EE) return;
    bool pos = w < EE;
    int e = pos ? w : w - EE;
    int uN = pos ? src[e] : nsrc[e];
    int vN = pos ? dst[e] : ndst[e];

    uint4 up = ((const uint4*)(g_hh + uN * HD))[lane];
    uint4 vp = ((const uint4*)(g_hh + vN * HD))[lane];
    float2 u0 = __half22float2(*(__half2*)&up.x), v0 = __half22float2(*(__half2*)&vp.x);
    float2 u1 = __half22float2(*(__half2*)&up.y), v1 = __half22float2(*(__half2*)&vp.y);
    float2 u2 = __half22float2(*(__half2*)&up.z), v2 = __half22float2(*(__half2*)&vp.z);
    float2 u3 = __half22float2(*(__half2*)&up.w), v3 = __half22float2(*(__half2*)&vp.w);
    float d = u0.x * v0.x + u0.y * v0.y + u1.x * v1.x + u1.y * v1.y +
              u2.x * v2.x + u2.y * v2.y + u3.x * v3.x + u3.y * v3.y;
#pragma unroll
    for (int off = 4; off >= 1; off >>= 1) d += __shfl_down_sync(0xffffffffu, d, off, 8);
    if ((lane & 7) == 0) {
        int h = lane >> 3;
        out[(pos ? 0 : EE * HH) + e * HH + h] = d;
    }
}

// ---------------- launch -------------------------------------------------------
extern "C" void kernel_launch(void* const* d_in, const int* in_sizes, int n_in,
                              void* d_out, int out_size) {
    const float* x    = (const float*)d_in[0];
    const int* src    = (const int*)d_in[1];
    const int* dst    = (const int*)d_in[2];
    const int* nsrc   = (const int*)d_in[3];
    const int* ndst   = (const int*)d_in[4];
    const float* W[3]  = {(const float*)d_in[5], (const float*)d_in[9],  (const float*)d_in[13]};
    const float* al[3] = {(const float*)d_in[6], (const float*)d_in[10], (const float*)d_in[14]};
    const float* ar[3] = {(const float*)d_in[7], (const float*)d_in[11], (const float*)d_in[15]};
    const float* bb[3] = {(const float*)d_in[8], (const float*)d_in[12], (const float*)d_in[16]};
    float* out = (float*)d_out;

    float* hbuf = nullptr;
    cudaGetSymbolAddress((void**)&hbuf, g_h);
    __half* featbuf = nullptr;
    cudaGetSymbolAddress((void**)&featbuf, g_feat16);
    int* cntbuf = nullptr;
    cudaGetSymbolAddress((void**)&cntbuf, g_cnt);

    // --- CSR build (dst constant across layers) ---
    cudaMemsetAsync(cntbuf, 0, NN * sizeof(int));
    csr_hist_kernel<<<(EE + 255) / 256, 256>>>(dst);
    csr_scan_kernel<<<1, 1024>>>();
    csr_scatter_kernel<<<(EE + 255) / 256, 256>>>(src, dst);

    dim3 gemm_grid((NN + 127) / 128, 2);
    const int node_blocks  = (NN * 32 + 255) / 256;
    const int score_blocks = (2 * EE * 32 + 255) / 256;

    const float* layer_in = x;
    for (int l = 0; l < 3; l++) {
        gemm_fused<<<gemm_grid, 256>>>(layer_in, W[l], al[l], ar[l], featbuf);
        if (l == 2)
            fused_edge_kernel<true><<<node_blocks, 256>>>(bb[l]);
        else
            fused_edge_kernel<false><<<node_blocks, 256>>>(bb[l]);
        layer_in = hbuf;
    }
    score_kernel<<<score_blocks, 256>>>(src, dst, nsrc, ndst, out);
}